// round 4
// baseline (speedup 1.0000x reference)
#include <cuda_runtime.h>

#define S_LEN    2048
#define L        50
#define LP       52        // padded row stride (16B aligned: 208B)
#define NPACK    26        // f32x2 pairs along the sum dimension
#define TILE     32
#define RROWS    (TILE + 6)
#define ITERS    3
#define NTHREADS 256

typedef unsigned long long ull;

__device__ __forceinline__ ull pack2(float x, float y) {
    ull r; asm("mov.b64 %0, {%1, %2};" : "=l"(r) : "f"(x), "f"(y)); return r;
}
__device__ __forceinline__ void fma2(ull& d, ull a, ull b) {
    asm("fma.rn.f32x2 %0, %1, %2, %0;" : "+l"(d) : "l"(a), "l"(b));
}
__device__ __forceinline__ float sum2(ull v) {
    float lo, hi; asm("mov.b64 {%0, %1}, %2;" : "=f"(lo), "=f"(hi) : "l"(v));
    return lo + hi;
}

__global__ __launch_bounds__(NTHREADS, 2) void mfvi_kernel(
    const float* __restrict__ unary,
    const float* __restrict__ mask,
    const float* __restrict__ Tg,
    const float* __restrict__ tstart,
    const float* __restrict__ tend,
    float* __restrict__ out)
{
    __shared__ alignas(16) float u [RROWS][LP];
    __shared__ alignas(16) float qA[RROWS][LP];
    __shared__ alignas(16) float qB[RROWS][LP];
    __shared__ alignas(16) float sP[RROWS][LP];
    __shared__ alignas(16) float zr[LP];
    __shared__ float msm[RROWS];

    const int n    = blockIdx.y;
    const int p0   = blockIdx.x * TILE;
    const int base = p0 - 3;
    const int tid  = threadIdx.x;
    const int role = tid >> 7;            // 0 = minus (left msg), 1 = plus (right msg)
    const int rg   = (tid >> 6) & 1;      // row subgroup within role
    const int t    = tid & 63;            // label slot (valid t < 50)
    const int warp = tid >> 5;
    const int lane = tid & 31;

    // ---- role-specific transition data, packed pairwise along sum dim ----
    // minus: Tp[i] = (T[2i][t], T[2i+1][t])   (computes p_left @ T)
    // plus : Tp[i] = (T[t][2i], T[t][2i+1])   (computes p_right @ T^T)
    ull Tp[NPACK];
    #pragma unroll
    for (int i = 0; i < NPACK; i++) Tp[i] = 0ull;
    if (t < L) {
        #pragma unroll
        for (int i = 0; i < NPACK; i++) {
            int a0 = 2 * i, a1 = 2 * i + 1;
            float lo, hi;
            if (role == 0) {
                lo = Tg[a0 * L + t];
                hi = (a1 < L) ? Tg[a1 * L + t] : 0.f;
            } else {
                lo = Tg[t * L + a0];
                hi = (a1 < L) ? Tg[t * L + a1] : 0.f;
            }
            Tp[i] = pack2(lo, hi);
        }
    }
    const float tsr = (t < L) ? tstart[t] : 0.f;   // used by minus role (pos 0)
    const float ter = (t < L) ? tend[t]   : 0.f;   // used by plus role (pos >= 1)

    // ---- load masked unary into smem (with halo), init buffers ----
    for (int idx = tid; idx < RROWS * LP; idx += NTHREADS) {
        int r = idx / LP, c = idx - r * LP;
        int g = base + r;
        float v = 0.f;
        if (c < L && g >= 0 && g < S_LEN)
            v = unary[((size_t)n * S_LEN + g) * L + c] * mask[(size_t)n * S_LEN + g];
        u [r][c] = v;
        qA[r][c] = v;      // q0 = unary * mask
        qB[r][c] = 0.f;    // pads (c >= 50) stay 0 forever
        sP[r][c] = 0.f;
    }
    for (int r = tid; r < RROWS; r += NTHREADS) {
        int g = base + r;
        msm[r] = (g >= 0 && g < S_LEN) ? mask[(size_t)n * S_LEN + g] : 0.f;
    }
    for (int c = tid; c < LP; c += NTHREADS) zr[c] = 0.f;
    __syncthreads();

    float (*qsrc)[LP] = qA;
    float (*qdst)[LP] = qB;

    #pragma unroll
    for (int it = 0; it < ITERS; it++) {
        // -------- softmax in-place on qsrc, two rows per warp interleaved --------
        {
            int glo = max(base + it, 0);
            int ghi = min(p0 + TILE + 3 - it, S_LEN);
            int rlo = glo - base, rhi = ghi - base;
            for (int r0 = rlo + warp * 2; r0 < rhi; r0 += 16) {
                int r1 = r0 + 1;
                bool has1 = (r1 < rhi);
                int rb = has1 ? r1 : r0;
                float a0 = qsrc[r0][lane];
                float a1 = (lane < L - 32) ? qsrc[r0][lane + 32] : -3.4e38f;
                float b0 = qsrc[rb][lane];
                float b1 = (lane < L - 32) ? qsrc[rb][lane + 32] : -3.4e38f;
                float ma = fmaxf(a0, a1);
                float mb = fmaxf(b0, b1);
                #pragma unroll
                for (int o = 16; o > 0; o >>= 1) {
                    ma = fmaxf(ma, __shfl_xor_sync(0xffffffffu, ma, o));
                    mb = fmaxf(mb, __shfl_xor_sync(0xffffffffu, mb, o));
                }
                float ea0 = __expf(a0 - ma);
                float ea1 = (lane < L - 32) ? __expf(a1 - ma) : 0.f;
                float eb0 = __expf(b0 - mb);
                float eb1 = (lane < L - 32) ? __expf(b1 - mb) : 0.f;
                float sa = ea0 + ea1, sb = eb0 + eb1;
                #pragma unroll
                for (int o = 16; o > 0; o >>= 1) {
                    sa += __shfl_xor_sync(0xffffffffu, sa, o);
                    sb += __shfl_xor_sync(0xffffffffu, sb, o);
                }
                float ia = __fdividef(1.f, sa);
                float ib = __fdividef(1.f, sb);
                qsrc[r0][lane] = ea0 * ia;
                if (lane < L - 32) qsrc[r0][lane + 32] = ea1 * ia;
                if (has1) {
                    qsrc[r1][lane] = eb0 * ib;
                    if (lane < L - 32) qsrc[r1][lane + 32] = eb1 * ib;
                }
            }
        }
        __syncthreads();

        // -------- messages: each role computes one matvec per dest row --------
        {
            int glo = max(base + it + 1, 0);
            int ghi = min(p0 + TILE + 3 - (it + 1), S_LEN);
            int rlo = glo - base, rhi = ghi - base;
            for (int d0 = rlo + rg * 2; d0 < rhi; d0 += 4) {
                int d1 = d0 + 1;
                bool has1 = (d1 < rhi);
                int g0 = base + d0;
                const float *s0, *s1;
                if (role == 0) {
                    s0 = (g0 == 0) ? zr : qsrc[d0 - 1];
                    s1 = qsrc[d0];                      // d1-1 == d0 ; g1>=1 always
                } else {
                    s0 = (g0 == S_LEN - 1) ? zr : qsrc[d0 + 1];
                    s1 = (!has1 || g0 + 1 == S_LEN - 1) ? zr : qsrc[d1 + 1];
                }
                ull aA = 0ull, aB = 0ull, bA = 0ull, bB = 0ull;
                #pragma unroll
                for (int i = 0; i < NPACK; i += 2) {
                    ulonglong2 x2 = *(const ulonglong2*)(s0 + 2 * i);
                    ulonglong2 y2 = *(const ulonglong2*)(s1 + 2 * i);
                    fma2(aA, x2.x, Tp[i]);  fma2(aB, x2.y, Tp[i + 1]);
                    fma2(bA, y2.x, Tp[i]);  fma2(bB, y2.y, Tp[i + 1]);
                }
                float accA = sum2(aA) + sum2(aB);
                float accB = sum2(bA) + sum2(bB);
                if (role == 0) {
                    // pos 0: tstart replaces left matvec (zr gives 0 matvec)
                    accA += (g0 == 0) ? tsr : 0.f;
                } else {
                    // every pos >= 1 gets tend added to s_plus
                    accA += (g0 > 0) ? ter : 0.f;
                    accB += ter;                        // g1 = g0+1 >= 1 always
                }
                if (t < L) {
                    float (*dstp)[LP] = (role == 0) ? qdst : sP;
                    dstp[d0][t] = accA;
                    if (has1) dstp[d1][t] = accB;
                }
            }
        }
        __syncthreads();

        // -------- combine: qdst = (u + s_minus + s_plus) * mask --------
        {
            int glo = max(base + it + 1, 0);
            int ghi = min(p0 + TILE + 3 - (it + 1), S_LEN);
            int rlo = glo - base, rhi = ghi - base;
            int cnt = (rhi - rlo) * L;
            for (int idx = tid; idx < cnt; idx += NTHREADS) {
                int r = rlo + idx / L, c = idx - (idx / L) * L;
                qdst[r][c] = (u[r][c] + qdst[r][c] + sP[r][c]) * msm[r];
            }
        }
        __syncthreads();

        float (*tmp)[LP] = qsrc; qsrc = qdst; qdst = tmp;
    }

    // ---- write final tile rows [p0, p0+TILE) (result lives in qsrc) ----
    for (int idx = tid; idx < TILE * L; idx += NTHREADS) {
        int r = idx / L, c = idx - r * L;
        out[((size_t)n * S_LEN + p0 + r) * L + c] = qsrc[3 + r][c];
    }
}

extern "C" void kernel_launch(void* const* d_in, const int* in_sizes, int n_in,
                              void* d_out, int out_size)
{
    const float* unary = (const float*)d_in[0];
    const float* mask  = (const float*)d_in[1];
    const float* T     = (const float*)d_in[2];
    const float* ts    = (const float*)d_in[3];
    const float* te    = (const float*)d_in[4];
    (void)n_in; (void)out_size;

    int NS = in_sizes[1];
    int N  = NS / S_LEN;
    dim3 grid(S_LEN / TILE, N);
    mfvi_kernel<<<grid, NTHREADS>>>(unary, mask, T, ts, te, (float*)d_out);
}

// round 5
// speedup vs baseline: 1.0916x; 1.0916x over previous
#include <cuda_runtime.h>

#define S_LEN    2048
#define L        50
#define LP       52        // padded row stride (16B aligned: 208B)
#define TILE     32
#define RROWS    (TILE + 6)
#define ITERS    3
#define NTHREADS 256

typedef unsigned long long ull;

__device__ __forceinline__ ull pack2(float x, float y) {
    ull r; asm("mov.b64 %0, {%1, %2};" : "=l"(r) : "f"(x), "f"(y)); return r;
}
__device__ __forceinline__ void fma2(ull& d, ull a, ull b) {
    asm("fma.rn.f32x2 %0, %1, %2, %0;" : "+l"(d) : "l"(a), "l"(b));
}
__device__ __forceinline__ float sum2(ull v) {
    float lo, hi; asm("mov.b64 {%0, %1}, %2;" : "=f"(lo), "=f"(hi) : "l"(v));
    return lo + hi;
}

__global__ __launch_bounds__(NTHREADS, 4) void mfvi_kernel(
    const float* __restrict__ unary,
    const float* __restrict__ mask,
    const float* __restrict__ Tg,
    const float* __restrict__ tstart,
    const float* __restrict__ tend,
    float* __restrict__ out)
{
    // 5 tile arrays: q ping-pong + 3 partial-message scratch (qdst doubles as 4th)
    __shared__ alignas(16) float qA [RROWS][LP];
    __shared__ alignas(16) float qB [RROWS][LP];
    __shared__ alignas(16) float sM1[RROWS][LP];
    __shared__ alignas(16) float sP0[RROWS][LP];
    __shared__ alignas(16) float sP1[RROWS][LP];
    __shared__ alignas(16) float zr[LP];
    __shared__ float msm[RROWS];

    const int n    = blockIdx.y;
    const int p0   = blockIdx.x * TILE;
    const int base = p0 - 3;
    const int tid  = threadIdx.x;
    const int grp  = tid >> 6;            // 4 groups of 64 threads
    const int role = grp & 1;             // 0 = minus (left msg), 1 = plus (right msg)
    const int half = grp >> 1;            // sum-dim half: 0 -> [0,28), 1 -> [28,52)
    const int t    = tid & 63;            // label slot (valid t < 50)
    const int warp = tid >> 5;
    const int lane = tid & 31;

    const int hoff = half ? 28 : 0;       // float offset (16B aligned: 0 / 112B)
    const int nv   = half ? 6  : 7;       // # ulonglong2 (4-float) chunks in this half

    // ---- quarter of transition data per thread, packed pairwise ----
    // minus: Tp[j] = (T[a][t], T[a+1][t])   plus: Tp[j] = (T[t][a], T[t][a+1])
    ull Tp[14];
    #pragma unroll
    for (int j = 0; j < 14; j++) Tp[j] = 0ull;
    if (t < L) {
        #pragma unroll
        for (int j = 0; j < 14; j++) {
            int a0 = hoff + 2 * j, a1 = a0 + 1;
            if (a0 >= hoff + (half ? 24 : 28)) break;
            float lo = 0.f, hi = 0.f;
            if (role == 0) {
                if (a0 < L) lo = Tg[a0 * L + t];
                if (a1 < L) hi = Tg[a1 * L + t];
            } else {
                if (a0 < L) lo = Tg[t * L + a0];
                if (a1 < L) hi = Tg[t * L + a1];
            }
            Tp[j] = pack2(lo, hi);
        }
    }
    const float tsr = (t < L) ? tstart[t] : 0.f;   // added by (minus, h0) at pos 0
    const float ter = (t < L) ? tend[t]   : 0.f;   // added by (plus,  h0) at pos >= 1

    // ---- init: qA = unary*mask (with halo), qB = 0 (pads stay 0 forever) ----
    for (int idx = tid; idx < RROWS * LP; idx += NTHREADS) {
        int r = idx / LP, c = idx - r * LP;
        int g = base + r;
        float v = 0.f;
        if (c < L && g >= 0 && g < S_LEN)
            v = unary[((size_t)n * S_LEN + g) * L + c] * mask[(size_t)n * S_LEN + g];
        qA[r][c] = v;
        qB[r][c] = 0.f;
    }
    for (int r = tid; r < RROWS; r += NTHREADS) {
        int g = base + r;
        msm[r] = (g >= 0 && g < S_LEN) ? mask[(size_t)n * S_LEN + g] : 0.f;
    }
    for (int c = tid; c < LP; c += NTHREADS) zr[c] = 0.f;
    __syncthreads();

    float (*qsrc)[LP] = qA;
    float (*qdst)[LP] = qB;

    #pragma unroll
    for (int it = 0; it < ITERS; it++) {
        // -------- softmax in-place on qsrc, two rows per warp interleaved --------
        {
            int glo = max(base + it, 0);
            int ghi = min(p0 + TILE + 3 - it, S_LEN);
            int rlo = glo - base, rhi = ghi - base;
            for (int r0 = rlo + warp * 2; r0 < rhi; r0 += 16) {
                int r1 = r0 + 1;
                bool has1 = (r1 < rhi);
                int rb = has1 ? r1 : r0;
                float a0 = qsrc[r0][lane];
                float a1 = (lane < L - 32) ? qsrc[r0][lane + 32] : -3.4e38f;
                float b0 = qsrc[rb][lane];
                float b1 = (lane < L - 32) ? qsrc[rb][lane + 32] : -3.4e38f;
                float ma = fmaxf(a0, a1), mb = fmaxf(b0, b1);
                #pragma unroll
                for (int o = 16; o > 0; o >>= 1) {
                    ma = fmaxf(ma, __shfl_xor_sync(0xffffffffu, ma, o));
                    mb = fmaxf(mb, __shfl_xor_sync(0xffffffffu, mb, o));
                }
                float ea0 = __expf(a0 - ma);
                float ea1 = (lane < L - 32) ? __expf(a1 - ma) : 0.f;
                float eb0 = __expf(b0 - mb);
                float eb1 = (lane < L - 32) ? __expf(b1 - mb) : 0.f;
                float sa = ea0 + ea1, sb = eb0 + eb1;
                #pragma unroll
                for (int o = 16; o > 0; o >>= 1) {
                    sa += __shfl_xor_sync(0xffffffffu, sa, o);
                    sb += __shfl_xor_sync(0xffffffffu, sb, o);
                }
                float ia = __fdividef(1.f, sa);
                float ib = __fdividef(1.f, sb);
                qsrc[r0][lane] = ea0 * ia;
                if (lane < L - 32) qsrc[r0][lane + 32] = ea1 * ia;
                if (has1) {
                    qsrc[r1][lane] = eb0 * ib;
                    if (lane < L - 32) qsrc[r1][lane + 32] = eb1 * ib;
                }
            }
        }
        __syncthreads();

        int glo = max(base + it + 1, 0);
        int ghi = min(p0 + TILE + 3 - (it + 1), S_LEN);
        int rlo = glo - base, rhi = ghi - base;

        // -------- partial messages: every group does all rows, quarter dot --------
        {
            float (*dstp)[LP] = (grp == 0) ? qdst : (grp == 1) ? sP0
                               : (grp == 2) ? sM1 : sP1;
            for (int d0 = rlo; d0 < rhi; d0 += 2) {
                int d1 = d0 + 1;
                bool has1 = (d1 < rhi);
                int g0 = base + d0;
                const float *s0, *s1;
                if (role == 0) {
                    s0 = (g0 == 0) ? zr : qsrc[d0 - 1];
                    s1 = qsrc[d0];                       // row d1's left neighbor
                } else {
                    s0 = (g0 == S_LEN - 1) ? zr : qsrc[d0 + 1];
                    s1 = (!has1 || g0 + 1 == S_LEN - 1) ? zr : qsrc[d0 + 2];
                }
                const float* p0f = s0 + hoff;
                const float* p1f = s1 + hoff;
                ull aA = 0ull, aB = 0ull, bA = 0ull, bB = 0ull;
                #pragma unroll
                for (int i = 0; i < 7; i++) {
                    if (i < nv) {                        // warp-uniform branch
                        ulonglong2 x2 = *(const ulonglong2*)(p0f + 4 * i);
                        ulonglong2 y2 = *(const ulonglong2*)(p1f + 4 * i);
                        fma2(aA, x2.x, Tp[2 * i]);  fma2(aB, x2.y, Tp[2 * i + 1]);
                        fma2(bA, y2.x, Tp[2 * i]);  fma2(bB, y2.y, Tp[2 * i + 1]);
                    }
                }
                float accA = sum2(aA) + sum2(aB);
                float accB = sum2(bA) + sum2(bB);
                if (half == 0) {
                    if (role == 0) accA += (g0 == 0) ? tsr : 0.f;   // pos 0: tstart
                    else { accA += (g0 > 0) ? ter : 0.f; accB += ter; } // pos>=1: tend
                }
                if (t < L) {
                    dstp[d0][t] = accA;
                    if (has1) dstp[d1][t] = accB;
                }
            }
        }
        __syncthreads();

        // -------- combine: qdst = (unary*m + sum of 4 partials) * m --------
        {
            int cnt = (rhi - rlo) * L;
            for (int idx = tid; idx < cnt; idx += NTHREADS) {
                int rr = idx / L, c = idx - rr * L;
                int r = rlo + rr;
                int g = base + r;
                float uv = unary[((size_t)n * S_LEN + g) * L + c];
                float m  = msm[r];
                qdst[r][c] = (uv * m + qdst[r][c] + sM1[r][c]
                              + sP0[r][c] + sP1[r][c]) * m;
            }
        }
        __syncthreads();

        float (*tmp)[LP] = qsrc; qsrc = qdst; qdst = tmp;
    }

    // ---- write final tile rows [p0, p0+TILE) (result lives in qsrc) ----
    for (int idx = tid; idx < TILE * L; idx += NTHREADS) {
        int r = idx / L, c = idx - r * L;
        out[((size_t)n * S_LEN + p0 + r) * L + c] = qsrc[3 + r][c];
    }
}

extern "C" void kernel_launch(void* const* d_in, const int* in_sizes, int n_in,
                              void* d_out, int out_size)
{
    const float* unary = (const float*)d_in[0];
    const float* mask  = (const float*)d_in[1];
    const float* T     = (const float*)d_in[2];
    const float* ts    = (const float*)d_in[3];
    const float* te    = (const float*)d_in[4];
    (void)n_in; (void)out_size;

    int NS = in_sizes[1];
    int N  = NS / S_LEN;
    dim3 grid(S_LEN / TILE, N);
    mfvi_kernel<<<grid, NTHREADS>>>(unary, mask, T, ts, te, (float*)d_out);
}

// round 6
// speedup vs baseline: 1.0979x; 1.0058x over previous
#include <cuda_runtime.h>

#define S_LEN    2048
#define L        50
#define LP       52
#define TILE     64
#define RROWS    (TILE + 6)
#define ITERS    3
#define NTHREADS 256

typedef unsigned long long ull;

__device__ __forceinline__ ull pack2(float x, float y) {
    ull r; asm("mov.b64 %0, {%1, %2};" : "=l"(r) : "f"(x), "f"(y)); return r;
}
__device__ __forceinline__ void fma2(ull& d, ull a, ull b) {
    asm("fma.rn.f32x2 %0, %1, %2, %0;" : "+l"(d) : "l"(a), "l"(b));
}
__device__ __forceinline__ float sum2(ull v) {
    float lo, hi; asm("mov.b64 {%0, %1}, %2;" : "=f"(lo), "=f"(hi) : "l"(v));
    return lo + hi;
}

__global__ __launch_bounds__(NTHREADS, 4) void mfvi_kernel(
    const float* __restrict__ unary,
    const float* __restrict__ mask,
    const float* __restrict__ Tg,
    const float* __restrict__ tstart,
    const float* __restrict__ tend,
    float* __restrict__ out)
{
    __shared__ alignas(16) float qP[RROWS][LP];   // probabilities (softmax output)
    __shared__ alignas(16) float sN[RROWS][LP];   // u*m + accumulated messages
    __shared__ alignas(16) float zr[LP];
    __shared__ float msm[RROWS];

    const int n    = blockIdx.y;
    const int p0   = blockIdx.x * TILE;
    const int base = p0 - 3;
    const int tid  = threadIdx.x;
    const int warp = tid >> 5;
    const int lane = tid & 31;
    const int role = warp & 1;            // 0 = minus (left msg), 1 = plus (right msg)
    const int ch   = warp >> 1;           // sum-dim chunk 0..3

    // chunk float ranges: [0,16) [16,28) [28,40) [40,52)  (all 16B-aligned offsets)
    const int off = (ch == 0) ? 0 : (ch == 1) ? 16 : (ch == 2) ? 28 : 40;
    const int nv  = (ch == 0) ? 4 : 3;    // ulonglong2 (4-float) loads per chunk

    const int  t0   = lane;               // first label (always < 50)
    const int  t1   = lane + 32;          // second label
    const bool t1ok = (t1 < L);

    // ---- transition chunk for both labels, packed pairwise along sum dim ----
    // minus: Tp[j] = (T[a][t], T[a+1][t])   plus: Tp[j] = (T[t][a], T[t][a+1])
    ull Tp0[8], Tp1[8];
    #pragma unroll
    for (int j = 0; j < 8; j++) { Tp0[j] = 0ull; Tp1[j] = 0ull; }
    #pragma unroll
    for (int j = 0; j < 8; j++) {
        if (j < 2 * nv) {
            int a0 = off + 2 * j, a1 = a0 + 1;
            float l0 = 0.f, h0 = 0.f, l1 = 0.f, h1 = 0.f;
            if (role == 0) {
                if (a0 < L) l0 = Tg[a0 * L + t0];
                if (a1 < L) h0 = Tg[a1 * L + t0];
                if (t1ok) {
                    if (a0 < L) l1 = Tg[a0 * L + t1];
                    if (a1 < L) h1 = Tg[a1 * L + t1];
                }
            } else {
                if (a0 < L) l0 = Tg[t0 * L + a0];
                if (a1 < L) h0 = Tg[t0 * L + a1];
                if (t1ok) {
                    if (a0 < L) l1 = Tg[t1 * L + a0];
                    if (a1 < L) h1 = Tg[t1 * L + a1];
                }
            }
            Tp0[j] = pack2(l0, h0);
            Tp1[j] = pack2(l1, h1);
        }
    }
    const float tsr0 = tstart[t0];
    const float tsr1 = t1ok ? tstart[t1] : 0.f;
    const float ter0 = tend[t0];
    const float ter1 = t1ok ? tend[t1] : 0.f;

    // ---- init: mask row cache, zero row, qP pads ----
    for (int r = tid; r < RROWS; r += NTHREADS) {
        int g = base + r;
        msm[r]    = (g >= 0 && g < S_LEN) ? mask[(size_t)n * S_LEN + g] : 0.f;
        qP[r][50] = 0.f;
        qP[r][51] = 0.f;
    }
    for (int c = tid; c < LP; c += NTHREADS) zr[c] = 0.f;
    __syncthreads();

    #pragma unroll
    for (int it = 0; it < ITERS; it++) {
        // ==== pass S: q = sN*m (or u*m at it=0); re-init sN = u*m; p = softmax(q) ====
        {
            int glo = max(base + it, 0);
            int ghi = min(p0 + TILE + 3 - it, S_LEN);
            int rlo = glo - base, rhi = ghi - base;
            for (int r0 = rlo + warp * 2; r0 < rhi; r0 += 16) {
                int r1 = r0 + 1;
                bool has1 = (r1 < rhi);
                int rb = has1 ? r1 : r0;
                float m0 = msm[r0], mb = msm[rb];
                const float* U0 = unary + ((size_t)n * S_LEN + (base + r0)) * L;
                const float* Ub = unary + ((size_t)n * S_LEN + (base + rb)) * L;
                float u00 = U0[t0], ub0 = Ub[t0];
                float u01 = t1ok ? U0[t1] : 0.f;
                float ub1 = t1ok ? Ub[t1] : 0.f;

                float v00, v01, vb0, vb1;
                if (it == 0) {
                    v00 = u00 * m0;  v01 = t1ok ? u01 * m0 : -3.4e38f;
                    vb0 = ub0 * mb;  vb1 = t1ok ? ub1 * mb : -3.4e38f;
                } else {
                    v00 = sN[r0][t0] * m0;
                    v01 = t1ok ? sN[r0][t1] * m0 : -3.4e38f;
                    vb0 = sN[rb][t0] * mb;
                    vb1 = t1ok ? sN[rb][t1] * mb : -3.4e38f;
                }
                // re-init accumulator for this iteration's message pass
                sN[r0][t0] = u00 * m0;
                if (t1ok) sN[r0][t1] = u01 * m0;
                sN[rb][t0] = ub0 * mb;
                if (t1ok) sN[rb][t1] = ub1 * mb;

                float ma = fmaxf(v00, v01), mbv = fmaxf(vb0, vb1);
                #pragma unroll
                for (int o = 16; o > 0; o >>= 1) {
                    ma  = fmaxf(ma,  __shfl_xor_sync(0xffffffffu, ma,  o));
                    mbv = fmaxf(mbv, __shfl_xor_sync(0xffffffffu, mbv, o));
                }
                float e00 = __expf(v00 - ma);
                float e01 = t1ok ? __expf(v01 - ma) : 0.f;
                float eb0 = __expf(vb0 - mbv);
                float eb1 = t1ok ? __expf(vb1 - mbv) : 0.f;
                float sa = e00 + e01, sb = eb0 + eb1;
                #pragma unroll
                for (int o = 16; o > 0; o >>= 1) {
                    sa += __shfl_xor_sync(0xffffffffu, sa, o);
                    sb += __shfl_xor_sync(0xffffffffu, sb, o);
                }
                float ia = __fdividef(1.f, sa);
                float ib = __fdividef(1.f, sb);
                qP[r0][t0] = e00 * ia;
                if (t1ok) qP[r0][t1] = e01 * ia;
                if (has1) {
                    qP[r1][t0] = eb0 * ib;
                    if (t1ok) qP[r1][t1] = eb1 * ib;
                }
            }
        }
        __syncthreads();

        // ==== pass M: all 8 warps sweep all dest rows; chunk partial -> atomicAdd ====
        {
            int dlo = max(base + it + 1, 0) - base;
            int dhi = min(p0 + TILE + 2 - it, S_LEN) - base;
            for (int d0 = dlo; d0 < dhi; d0 += 2) {
                int d1 = d0 + 1;
                bool has1 = (d1 < dhi);
                int g0 = base + d0;
                const float *s0, *s1;
                if (role == 0) {
                    s0 = (g0 == 0) ? zr : qP[d0 - 1];
                    s1 = qP[d0];                            // d1's left neighbor
                } else {
                    s0 = (g0 == S_LEN - 1) ? zr : qP[d0 + 1];
                    s1 = (!has1 || g0 + 1 == S_LEN - 1) ? zr : qP[d0 + 2];
                }
                const float* pa = s0 + off;
                const float* pb = s1 + off;
                ull a0 = 0ull, a1 = 0ull, b0 = 0ull, b1 = 0ull;
                #pragma unroll
                for (int i = 0; i < 4; i++) {
                    if (i < nv) {                           // warp-uniform
                        ulonglong2 x2 = *(const ulonglong2*)(pa + 4 * i);
                        ulonglong2 y2 = *(const ulonglong2*)(pb + 4 * i);
                        fma2(a0, x2.x, Tp0[2 * i]);  fma2(a0, x2.y, Tp0[2 * i + 1]);
                        fma2(a1, x2.x, Tp1[2 * i]);  fma2(a1, x2.y, Tp1[2 * i + 1]);
                        fma2(b0, y2.x, Tp0[2 * i]);  fma2(b0, y2.y, Tp0[2 * i + 1]);
                        fma2(b1, y2.x, Tp1[2 * i]);  fma2(b1, y2.y, Tp1[2 * i + 1]);
                    }
                }
                float A0 = sum2(a0), A1 = sum2(a1);
                float B0 = sum2(b0), B1 = sum2(b1);
                if (ch == 0) {                              // boundary terms once
                    if (role == 0) {
                        if (g0 == 0) { A0 += tsr0; A1 += tsr1; }   // pos0: tstart
                    } else {
                        if (g0 > 0)  { A0 += ter0; A1 += ter1; }   // pos>=1: tend
                        B0 += ter0; B1 += ter1;                    // g1 >= 1 always
                    }
                }
                atomicAdd(&sN[d0][t0], A0);
                if (t1ok) atomicAdd(&sN[d0][t1], A1);
                if (has1) {
                    atomicAdd(&sN[d1][t0], B0);
                    if (t1ok) atomicAdd(&sN[d1][t1], B1);
                }
            }
        }
        __syncthreads();
    }

    // ==== final: q3 = sN * m, straight to global ====
    for (int idx = tid; idx < TILE * L; idx += NTHREADS) {
        int r = idx / L, c = idx - r * L;
        out[((size_t)n * S_LEN + p0 + r) * L + c] = sN[3 + r][c] * msm[3 + r];
    }
}

extern "C" void kernel_launch(void* const* d_in, const int* in_sizes, int n_in,
                              void* d_out, int out_size)
{
    const float* unary = (const float*)d_in[0];
    const float* mask  = (const float*)d_in[1];
    const float* T     = (const float*)d_in[2];
    const float* ts    = (const float*)d_in[3];
    const float* te    = (const float*)d_in[4];
    (void)n_in; (void)out_size;

    int NS = in_sizes[1];
    int N  = NS / S_LEN;
    dim3 grid(S_LEN / TILE, N);
    mfvi_kernel<<<grid, NTHREADS>>>(unary, mask, T, ts, te, (float*)d_out);
}

// round 8
// speedup vs baseline: 1.2535x; 1.1417x over previous
#include <cuda_runtime.h>
#include <cstdint>

#define S_LEN    2048
#define L        50
#define TILE     122
#define RROWS    128
#define NTHREADS 256
#define NTILES   ((S_LEN + TILE - 1) / TILE)

#define AST 132   // A stride (floats); 132 % 32 == 4 -> conflict-free frags
#define BST 132
#define DST 66
#define UST 53

// smem byte offsets from 1024-aligned base
#define OFF_A    0u
#define OFF_BHI  67584u
#define OFF_BLO  101376u
#define OFF_D    135168u
#define OFF_U    168960u
#define OFF_MSK  196096u
#define OFF_TS   196608u
#define OFF_TE   196864u
#define SMEM_BYTES (197120 + 1024)

__device__ __forceinline__ uint32_t tf32b(float x) {
    uint32_t u; asm("cvt.rna.tf32.f32 %0, %1;" : "=r"(u) : "f"(x)); return u;
}
__device__ __forceinline__ void mma8(float* d, uint32_t a0, uint32_t a1,
                                     uint32_t a2, uint32_t a3,
                                     uint32_t b0, uint32_t b1) {
    asm volatile(
        "mma.sync.aligned.m16n8k8.row.col.f32.tf32.tf32.f32 "
        "{%0,%1,%2,%3}, {%4,%5,%6,%7}, {%8,%9}, {%0,%1,%2,%3};"
        : "+f"(d[0]), "+f"(d[1]), "+f"(d[2]), "+f"(d[3])
        : "r"(a0), "r"(a1), "r"(a2), "r"(a3), "r"(b0), "r"(b1));
}

__global__ __launch_bounds__(NTHREADS) void mfvi_kernel(
    const float* __restrict__ unary,
    const float* __restrict__ mask,
    const float* __restrict__ Tg,
    const float* __restrict__ tstart,
    const float* __restrict__ tend,
    float* __restrict__ out)
{
    extern __shared__ char dsm_raw[];
    char* smp = (char*)(((uintptr_t)dsm_raw + 1023) & ~(uintptr_t)1023);
    float* As  = (float*)(smp + OFF_A);
    float* Bhi = (float*)(smp + OFF_BHI);
    float* Blo = (float*)(smp + OFF_BLO);
    float* Dsm = (float*)(smp + OFF_D);
    float* Usm = (float*)(smp + OFF_U);
    float* Msk = (float*)(smp + OFF_MSK);
    float* Tss = (float*)(smp + OFF_TS);
    float* Tes = (float*)(smp + OFF_TE);

    const int n    = blockIdx.y;
    const int p0   = blockIdx.x * TILE;
    const int base = p0 - 3;
    const int tid  = threadIdx.x;
    const int r    = tid;                       // tile row for build phase
    const int g    = base + r;
    const bool rowok = (tid < 128) && (g >= 0) && (g < S_LEN);

    // ---- prologue ----
    {   // zero A (incl. k-pads 50..63, 114..127 — they must stay 0)
        float4 z = make_float4(0.f, 0.f, 0.f, 0.f);
        for (int i = tid; i < RROWS * AST / 4; i += NTHREADS)
            ((float4*)As)[i] = z;
    }
    // B'[n][k]: k<50 -> T[k][n]; 64<=k<114 -> T[n][k-64]; else 0. Split hi/lo.
    for (int idx = tid; idx < 64 * BST; idx += NTHREADS) {
        int bn = idx / BST, bk = idx - bn * BST;
        float v = 0.f;
        if (bn < L) {
            if (bk < L)                           v = Tg[bk * L + bn];
            else if (bk >= 64 && bk < 64 + L)     v = Tg[bn * L + (bk - 64)];
        }
        float hi = __uint_as_float(tf32b(v));
        Bhi[idx] = hi;
        Blo[idx] = __uint_as_float(tf32b(v - hi));
    }
    // masked unary rows + mask cache
    if (tid < 128)
        Msk[tid] = rowok ? mask[(size_t)n * S_LEN + g] : 0.f;
    __syncthreads();
    for (int idx = tid; idx < 128 * UST; idx += NTHREADS) {
        int rr = idx / UST, c = idx - rr * UST;
        int gg = base + rr;
        float v = 0.f;
        if (c < L && gg >= 0 && gg < S_LEN)
            v = unary[((size_t)n * S_LEN + gg) * L + c] * Msk[rr];
        Usm[idx] = v;
    }
    if (tid < 64) {
        Tss[tid] = (tid < L) ? tstart[tid] : 0.f;
        Tes[tid] = (tid < L) ? tend[tid]   : 0.f;
    }
    __syncthreads();

    #pragma unroll 1
    for (int it = 0; it <= 3; it++) {
        // ==== build phase: thread = row ====
        if (tid < 128) {
            const bool act = rowok && (r >= it) && (r < RROWS - it);
            if (act) {
                float q[52];
                if (it == 0) {
                    #pragma unroll
                    for (int c = 0; c < 50; c++) q[c] = Usm[r * UST + c];
                } else {
                    const float  m   = Msk[r];
                    const float* bnd = (g == 0) ? Tss : Tes;  // pos0: tstart; >=1: tend
                    #pragma unroll
                    for (int c = 0; c < 50; c++)
                        q[c] = (Usm[r * UST + c] + Dsm[r * DST + c] + bnd[c]) * m;
                }
                if (it == 3) {
                    float* st = As;                     // reuse A region as staging
                    #pragma unroll
                    for (int c = 0; c < 50; c++) st[(r - 3) * 50 + c] = q[c];
                } else {
                    float mx = q[0];
                    #pragma unroll
                    for (int c = 1; c < 50; c++) mx = fmaxf(mx, q[c]);
                    float s = 0.f;
                    #pragma unroll
                    for (int c = 0; c < 50; c++) { q[c] = __expf(q[c] - mx); s += q[c]; }
                    float inv = __fdividef(1.f, s);
                    #pragma unroll
                    for (int c = 0; c < 50; c++) q[c] *= inv;
                    q[50] = 0.f; q[51] = 0.f;
                    // p[r] is: left-neighbor content of row r+1 (k 0..49)
                    //          right-neighbor content of row r-1 (k 64..113)
                    #pragma unroll
                    for (int c4 = 0; c4 < 13; c4++) {
                        float4 v = make_float4(q[4*c4], q[4*c4+1], q[4*c4+2], q[4*c4+3]);
                        if (r + 1 < RROWS)
                            *(float4*)&As[(r + 1) * AST + 4 * c4] = v;
                        if (r - 1 >= 0)
                            *(float4*)&As[(r - 1) * AST + 64 + 4 * c4] = v;
                    }
                }
            }
        }
        __syncthreads();
        if (it == 3) break;

        // ==== MMA phase: 8 warps, warp w -> rows [16w,16w+16), all 64 cols ====
        {
            const int w   = tid >> 5;
            const int l   = tid & 31;
            const int gID = l >> 2;       // 0..7
            const int tID = l & 3;        // 0..3
            const int R0  = w * 16;

            float acc[8][4];
            #pragma unroll
            for (int nt = 0; nt < 8; nt++)
                #pragma unroll
                for (int j = 0; j < 4; j++) acc[nt][j] = 0.f;

            const float* Ar = As + (R0 + gID) * AST + tID;
            // K-steps 7 (k 56..63) and 15 (k 120..127) are all-zero padding: skip.
            #pragma unroll
            for (int ks = 0; ks < 15; ks++) {
                if (ks == 7) continue;
                const int k0 = 8 * ks;
                float a0f = Ar[k0],           a2f = Ar[k0 + 4];
                float a1f = Ar[8 * AST + k0], a3f = Ar[8 * AST + k0 + 4];
                uint32_t a0h = tf32b(a0f), a1h = tf32b(a1f);
                uint32_t a2h = tf32b(a2f), a3h = tf32b(a3f);
                uint32_t a0l = tf32b(a0f - __uint_as_float(a0h));
                uint32_t a1l = tf32b(a1f - __uint_as_float(a1h));
                uint32_t a2l = tf32b(a2f - __uint_as_float(a2h));
                uint32_t a3l = tf32b(a3f - __uint_as_float(a3h));
                #pragma unroll
                for (int nt = 0; nt < 8; nt++) {
                    const int bo = (nt * 8 + gID) * BST + k0 + tID;
                    uint32_t b0h = __float_as_uint(Bhi[bo]);
                    uint32_t b1h = __float_as_uint(Bhi[bo + 4]);
                    uint32_t b0l = __float_as_uint(Blo[bo]);
                    uint32_t b1l = __float_as_uint(Blo[bo + 4]);
                    mma8(acc[nt], a0h, a1h, a2h, a3h, b0h, b1h);
                    mma8(acc[nt], a0l, a1l, a2l, a3l, b0h, b1h);
                    mma8(acc[nt], a0h, a1h, a2h, a3h, b0l, b1l);
                }
            }
            // store D fragments: d0=D[R0+gID][nt*8+2tID], d1=+1, d2=row+8, d3=row+8,+1
            #pragma unroll
            for (int nt = 0; nt < 8; nt++) {
                int c0 = nt * 8 + 2 * tID;
                *(float2*)&Dsm[(R0 + gID) * DST + c0]     = make_float2(acc[nt][0], acc[nt][1]);
                *(float2*)&Dsm[(R0 + gID + 8) * DST + c0] = make_float2(acc[nt][2], acc[nt][3]);
            }
        }
        __syncthreads();
    }
    __syncthreads();

    // ---- epilogue: coalesced staging -> global ----
    {
        int rows = min(TILE, S_LEN - p0);
        int nvec = rows * L / 4;
        const float4* s4 = (const float4*)As;
        float4* o4 = (float4*)(out + ((size_t)n * S_LEN + p0) * L);
        for (int i = tid; i < nvec; i += NTHREADS) o4[i] = s4[i];
    }
}

extern "C" void kernel_launch(void* const* d_in, const int* in_sizes, int n_in,
                              void* d_out, int out_size)
{
    const float* unary = (const float*)d_in[0];
    const float* mask  = (const float*)d_in[1];
    const float* T     = (const float*)d_in[2];
    const float* ts    = (const float*)d_in[3];
    const float* te    = (const float*)d_in[4];
    (void)n_in; (void)out_size;

    cudaFuncSetAttribute(mfvi_kernel,
                         cudaFuncAttributeMaxDynamicSharedMemorySize, SMEM_BYTES);

    int NS = in_sizes[1];
    int N  = NS / S_LEN;
    dim3 grid(NTILES, N);
    mfvi_kernel<<<grid, NTHREADS, SMEM_BYTES>>>(unary, mask, T, ts, te, (float*)d_out);
}

// round 9
// speedup vs baseline: 1.4122x; 1.1266x over previous
#include <cuda_runtime.h>
#include <cstdint>

#define S_LEN    2048
#define L        50
#define TILE     122
#define RROWS    128
#define NTHREADS 512
#define NTILES   ((S_LEN + TILE - 1) / TILE)

#define AST 132   // A stride (floats); 132 % 32 == 4 -> conflict-free frag loads
#define DST 70    // conflict-free scalar reads + 8B-aligned float2 stores
#define UST 57

// smem byte offsets from 1024-aligned base
#define OFF_A    0u
#define OFF_BF   67584u       // B fragments: 7 nt x 14 ks x 32 lanes x float4
#define OFF_D    117760u
#define OFF_U    153600u
#define OFF_MSK  182784u
#define OFF_TS   183296u
#define OFF_TE   183552u
#define SMEM_BYTES (183808 + 1024)

__device__ __forceinline__ uint32_t tf32b(float x) {
    uint32_t u; asm("cvt.rna.tf32.f32 %0, %1;" : "=r"(u) : "f"(x)); return u;
}
__device__ __forceinline__ void mma8(float* d, uint32_t a0, uint32_t a1,
                                     uint32_t a2, uint32_t a3,
                                     uint32_t b0, uint32_t b1) {
    asm volatile(
        "mma.sync.aligned.m16n8k8.row.col.f32.tf32.tf32.f32 "
        "{%0,%1,%2,%3}, {%4,%5,%6,%7}, {%8,%9}, {%0,%1,%2,%3};"
        : "+f"(d[0]), "+f"(d[1]), "+f"(d[2]), "+f"(d[3])
        : "r"(a0), "r"(a1), "r"(a2), "r"(a3), "r"(b0), "r"(b1));
}

__global__ __launch_bounds__(NTHREADS, 1) void mfvi_kernel(
    const float* __restrict__ unary,
    const float* __restrict__ mask,
    const float* __restrict__ Tg,
    const float* __restrict__ tstart,
    const float* __restrict__ tend,
    float* __restrict__ out)
{
    extern __shared__ char dsm_raw[];
    char* smp = (char*)(((uintptr_t)dsm_raw + 1023) & ~(uintptr_t)1023);
    float*  As  = (float*)(smp + OFF_A);
    float4* Bf  = (float4*)(smp + OFF_BF);
    float*  Dsm = (float*)(smp + OFF_D);
    float*  Usm = (float*)(smp + OFF_U);
    float*  Msk = (float*)(smp + OFF_MSK);
    float*  Tss = (float*)(smp + OFF_TS);
    float*  Tes = (float*)(smp + OFF_TE);

    const int n    = blockIdx.y;
    const int p0   = blockIdx.x * TILE;
    const int base = p0 - 3;
    const int tid  = threadIdx.x;

    // ---- prologue: zero A (pads must stay 0 forever) ----
    {
        float4 z = make_float4(0.f, 0.f, 0.f, 0.f);
        for (int i = tid; i < RROWS * AST / 4; i += NTHREADS)
            ((float4*)As)[i] = z;
    }
    // ---- B fragments, pre-split tf32 hi/lo, in exact mma fragment order ----
    // B'[n][k]: k<50 -> T[k][n] ; 64<=k<114 -> T[n][k-64] ; else 0
    for (int idx = tid; idx < 7 * 14 * 32; idx += NTHREADS) {
        int lane = idx & 31, rem = idx >> 5;
        int ksi = rem % 14, nt = rem / 14;
        int gI = lane >> 2, tI = lane & 3;
        int bn = nt * 8 + gI;
        int ks = ksi + (ksi >= 7 ? 1 : 0);
        float b[2];
        #pragma unroll
        for (int h = 0; h < 2; h++) {
            int k = 8 * ks + tI + 4 * h;
            float v = 0.f;
            if (bn < L) {
                if (k < L)                        v = Tg[k * L + bn];
                else if (k >= 64 && k < 64 + L)   v = Tg[bn * L + (k - 64)];
            }
            b[h] = v;
        }
        float h0 = __uint_as_float(tf32b(b[0]));
        float h1 = __uint_as_float(tf32b(b[1]));
        Bf[idx] = make_float4(h0, h1,
                              __uint_as_float(tf32b(b[0] - h0)),
                              __uint_as_float(tf32b(b[1] - h1)));
    }
    if (tid < 128) {
        int g = base + tid;
        Msk[tid] = (g >= 0 && g < S_LEN) ? mask[(size_t)n * S_LEN + g] : 0.f;
    }
    if (tid < 64) {
        Tss[tid] = (tid < L) ? tstart[tid] : 0.f;
        Tes[tid] = (tid < L) ? tend[tid]   : 0.f;
    }
    __syncthreads();
    for (int idx = tid; idx < 128 * UST; idx += NTHREADS) {
        int rr = idx / UST, c = idx - rr * UST;
        int gg = base + rr;
        float v = 0.f;
        if (c < L && gg >= 0 && gg < S_LEN)
            v = unary[((size_t)n * S_LEN + gg) * L + c] * Msk[rr];
        Usm[idx] = v;
    }
    __syncthreads();

    #pragma unroll 1
    for (int it = 0; it <= 3; it++) {
        // ==== build phase: 2 threads per row (labels [0,25) / [25,50)) ====
        if (tid < 256) {
            const int r     = tid >> 1;
            const int cbase = (tid & 1) ? 25 : 0;
            const int g     = base + r;
            const bool act  = (g >= 0) && (g < S_LEN) && (r >= it) && (r < RROWS - it);

            float q[25];
            if (it == 0) {
                #pragma unroll
                for (int i = 0; i < 25; i++) q[i] = Usm[r * UST + cbase + i];
            } else {
                const float  m   = Msk[r];
                const float* bnd = (g == 0) ? Tss : Tes;  // pos0: tstart; >=1: tend
                #pragma unroll
                for (int i = 0; i < 25; i++)
                    q[i] = (Usm[r * UST + cbase + i] + Dsm[r * DST + cbase + i]
                            + bnd[cbase + i]) * m;
            }
            if (it == 3) {
                if (act) {
                    float* st = As;                       // reuse A as staging
                    #pragma unroll
                    for (int i = 0; i < 25; i++) st[(r - 3) * 50 + cbase + i] = q[i];
                }
            } else {
                float mx = q[0];
                #pragma unroll
                for (int i = 1; i < 25; i++) mx = fmaxf(mx, q[i]);
                mx = fmaxf(mx, __shfl_xor_sync(0xffffffffu, mx, 1));
                float s = 0.f;
                #pragma unroll
                for (int i = 0; i < 25; i++) { q[i] = __expf(q[i] - mx); s += q[i]; }
                s += __shfl_xor_sync(0xffffffffu, s, 1);
                float inv = __fdividef(1.f, s);
                if (act) {
                    // p[r] -> left-neighbor half of row r+1, right-neighbor half of r-1
                    if (r + 1 < RROWS) {
                        float* a1 = As + (r + 1) * AST + cbase;
                        #pragma unroll
                        for (int i = 0; i < 25; i++) a1[i] = q[i] * inv;
                    }
                    if (r - 1 >= 0) {
                        float* a2 = As + (r - 1) * AST + 64 + cbase;
                        #pragma unroll
                        for (int i = 0; i < 25; i++) a2[i] = q[i] * inv;
                    }
                }
            }
        }
        __syncthreads();
        if (it == 3) break;

        // ==== MMA: 16 warps = 8 row-blocks x 2 col-halves ====
        {
            const int w   = tid >> 5;
            const int l   = tid & 31;
            const int gID = l >> 2;
            const int tID = l & 3;
            const int R0  = 16 * (w >> 1);
            const int nt0 = (w & 1) ? 4 : 0;
            const int ntc = (w & 1) ? 3 : 4;

            float acc[4][4];
            #pragma unroll
            for (int j = 0; j < 4; j++)
                #pragma unroll
                for (int k = 0; k < 4; k++) acc[j][k] = 0.f;

            const float* Ar = As + (R0 + gID) * AST + tID;
            #pragma unroll
            for (int ksi = 0; ksi < 14; ksi++) {
                const int ks = ksi + (ksi >= 7 ? 1 : 0);
                const int k0 = 8 * ks;
                float a0f = Ar[k0],           a2f = Ar[k0 + 4];
                float a1f = Ar[8 * AST + k0], a3f = Ar[8 * AST + k0 + 4];
                uint32_t a0h = tf32b(a0f), a1h = tf32b(a1f);
                uint32_t a2h = tf32b(a2f), a3h = tf32b(a3f);
                uint32_t a0l = tf32b(a0f - __uint_as_float(a0h));
                uint32_t a1l = tf32b(a1f - __uint_as_float(a1h));
                uint32_t a2l = tf32b(a2f - __uint_as_float(a2h));
                uint32_t a3l = tf32b(a3f - __uint_as_float(a3h));
                const float4* bp = Bf + (nt0 * 14 + ksi) * 32 + l;
                #pragma unroll
                for (int j = 0; j < 4; j++) {
                    if (j < ntc) {                       // warp-uniform guard
                        float4 b = bp[j * 14 * 32];
                        uint32_t b0h = __float_as_uint(b.x);
                        uint32_t b1h = __float_as_uint(b.y);
                        uint32_t b0l = __float_as_uint(b.z);
                        uint32_t b1l = __float_as_uint(b.w);
                        mma8(acc[j], a0h, a1h, a2h, a3h, b0h, b1h);
                        mma8(acc[j], a0l, a1l, a2l, a3l, b0h, b1h);
                        mma8(acc[j], a0h, a1h, a2h, a3h, b0l, b1l);
                    }
                }
            }
            #pragma unroll
            for (int j = 0; j < 4; j++) {
                if (j < ntc) {
                    int c0 = (nt0 + j) * 8 + 2 * tID;
                    *(float2*)&Dsm[(R0 + gID) * DST + c0] =
                        make_float2(acc[j][0], acc[j][1]);
                    *(float2*)&Dsm[(R0 + gID + 8) * DST + c0] =
                        make_float2(acc[j][2], acc[j][3]);
                }
            }
        }
        __syncthreads();
    }

    // ---- epilogue: coalesced staging -> global ----
    {
        int rows = min(TILE, S_LEN - p0);
        int nvec = rows * L / 4;
        const float4* s4 = (const float4*)As;
        float4* o4 = (float4*)(out + ((size_t)n * S_LEN + p0) * L);
        for (int i = tid; i < nvec; i += NTHREADS) o4[i] = s4[i];
    }
}

extern "C" void kernel_launch(void* const* d_in, const int* in_sizes, int n_in,
                              void* d_out, int out_size)
{
    const float* unary = (const float*)d_in[0];
    const float* mask  = (const float*)d_in[1];
    const float* T     = (const float*)d_in[2];
    const float* ts    = (const float*)d_in[3];
    const float* te    = (const float*)d_in[4];
    (void)n_in; (void)out_size;

    cudaFuncSetAttribute(mfvi_kernel,
                         cudaFuncAttributeMaxDynamicSharedMemorySize, SMEM_BYTES);

    int NS = in_sizes[1];
    int N  = NS / S_LEN;
    dim3 grid(NTILES, N);
    mfvi_kernel<<<grid, NTHREADS, SMEM_BYTES>>>(unary, mask, T, ts, te, (float*)d_out);
}

// round 10
// speedup vs baseline: 1.7225x; 1.2197x over previous
#include <cuda_runtime.h>
#include <cuda_bf16.h>
#include <cstdint>

#define S_LEN    2048
#define L        50
#define TILE     122
#define RROWS    128
#define NTHREADS 512
#define NTILES   ((S_LEN + TILE - 1) / TILE)

#define AHW 68    // uint32 words per A row (136 bf16; 68 % 32 == 4 -> conflict-free)
#define DST 70
#define UST 57

// smem byte offsets from 1024-aligned base
#define OFF_AHI 0u
#define OFF_ALO 34816u
#define OFF_BF  69632u      // B frags: 7 nt x 8 ks x 32 lanes x uint4
#define OFF_D   98304u
#define OFF_U   134144u
#define OFF_MSK 163328u
#define OFF_TS  163840u
#define OFF_TE  164096u
#define SMEM_BYTES (164352 + 1024)

__device__ __forceinline__ uint32_t bfpack(float lo, float hi) {
    uint32_t r;
    asm("cvt.rn.bf16x2.f32 %0, %1, %2;" : "=r"(r) : "f"(hi), "f"(lo));
    return r;
}
__device__ __forceinline__ float bfhi(float v) {
    return __bfloat162float(__float2bfloat16_rn(v));
}
__device__ __forceinline__ void mma16(float* d, uint32_t a0, uint32_t a1,
                                      uint32_t a2, uint32_t a3,
                                      uint32_t b0, uint32_t b1) {
    asm volatile(
        "mma.sync.aligned.m16n8k16.row.col.f32.bf16.bf16.f32 "
        "{%0,%1,%2,%3}, {%4,%5,%6,%7}, {%8,%9}, {%0,%1,%2,%3};"
        : "+f"(d[0]), "+f"(d[1]), "+f"(d[2]), "+f"(d[3])
        : "r"(a0), "r"(a1), "r"(a2), "r"(a3), "r"(b0), "r"(b1));
}

__global__ __launch_bounds__(NTHREADS, 1) void mfvi_kernel(
    const float* __restrict__ unary,
    const float* __restrict__ mask,
    const float* __restrict__ Tg,
    const float* __restrict__ tstart,
    const float* __restrict__ tend,
    float* __restrict__ out)
{
    extern __shared__ char dsm_raw[];
    char* smp = (char*)(((uintptr_t)dsm_raw + 1023) & ~(uintptr_t)1023);
    uint32_t* AhiU = (uint32_t*)(smp + OFF_AHI);
    uint32_t* AloU = (uint32_t*)(smp + OFF_ALO);
    uint4*    Bf   = (uint4*)   (smp + OFF_BF);
    float*    Dsm  = (float*)   (smp + OFF_D);
    float*    Usm  = (float*)   (smp + OFF_U);
    float*    Msk  = (float*)   (smp + OFF_MSK);
    float*    Tss  = (float*)   (smp + OFF_TS);
    float*    Tes  = (float*)   (smp + OFF_TE);

    const int n    = blockIdx.y;
    const int p0   = blockIdx.x * TILE;
    const int base = p0 - 3;
    const int tid  = threadIdx.x;

    // ---- prologue: zero A hi+lo (pads/halo rows must stay 0) ----
    {
        float4 z = make_float4(0.f, 0.f, 0.f, 0.f);
        for (int i = tid; i < (int)(2 * 34816 / 16); i += NTHREADS)
            ((float4*)(smp + OFF_AHI))[i] = z;
    }
    // ---- B fragments, bf16 hi/lo, exact m16n8k16 col-major fragment order ----
    // B'[bn][k]: k<50 -> T[k][bn] ; 64<=k<114 -> T[bn][k-64] ; else 0
    for (int idx = tid; idx < 7 * 8 * 32; idx += NTHREADS) {
        int lane = idx & 31, rem = idx >> 5;
        int ks = rem & 7, nt = rem >> 3;
        int gI = lane >> 2, tI = lane & 3;
        int bn = nt * 8 + gI;
        int k0 = 16 * ks + 2 * tI;
        float v[4];
        #pragma unroll
        for (int h = 0; h < 4; h++) {
            int k = k0 + (h >> 1) * 8 + (h & 1);
            float val = 0.f;
            if (bn < L) {
                if (k < L)                        val = Tg[k * L + bn];
                else if (k >= 64 && k < 64 + L)   val = Tg[bn * L + (k - 64)];
            }
            v[h] = val;
        }
        uint4 o;
        o.x = bfpack(v[0], v[1]);
        o.y = bfpack(v[2], v[3]);
        o.z = bfpack(v[0] - bfhi(v[0]), v[1] - bfhi(v[1]));
        o.w = bfpack(v[2] - bfhi(v[2]), v[3] - bfhi(v[3]));
        Bf[idx] = o;
    }
    if (tid < 128) {
        int g = base + tid;
        Msk[tid] = (g >= 0 && g < S_LEN) ? mask[(size_t)n * S_LEN + g] : 0.f;
    }
    if (tid < 64) {
        Tss[tid] = (tid < L) ? tstart[tid] : 0.f;
        Tes[tid] = (tid < L) ? tend[tid]   : 0.f;
    }
    __syncthreads();
    for (int idx = tid; idx < 128 * UST; idx += NTHREADS) {
        int rr = idx / UST, c = idx - rr * UST;
        int gg = base + rr;
        float v = 0.f;
        if (c < L && gg >= 0 && gg < S_LEN)
            v = unary[((size_t)n * S_LEN + gg) * L + c] * Msk[rr];
        Usm[idx] = v;
    }
    __syncthreads();

    #pragma unroll 1
    for (int it = 0; it <= 3; it++) {
        // ==== build: 2 threads/row, labels [0,26) / [26,50) ====
        if (tid < 256) {
            const int r     = tid >> 1;
            const int ch    = tid & 1;
            const int cbase = ch ? 26 : 0;
            const int cnt   = ch ? 24 : 26;
            const int g     = base + r;
            const bool act  = (g >= 0) && (g < S_LEN) && (r >= it) && (r < RROWS - it);

            float q[26];
            if (it == 0) {
                #pragma unroll
                for (int i = 0; i < 26; i++) q[i] = Usm[r * UST + cbase + i];
            } else {
                const float  m   = Msk[r];
                const float* bnd = (g == 0) ? Tss : Tes;  // pos0: tstart; >=1: tend
                #pragma unroll
                for (int i = 0; i < 26; i++)
                    if (i < cnt)
                        q[i] = (Usm[r * UST + cbase + i] + Dsm[r * DST + cbase + i]
                                + bnd[cbase + i]) * m;
            }
            if (it == 3) {
                if (act) {
                    float* st = (float*)(smp + OFF_AHI);   // reuse A as staging
                    #pragma unroll
                    for (int i = 0; i < 26; i++)
                        if (i < cnt) st[(r - 3) * 50 + cbase + i] = q[i];
                }
            } else {
                float mx = -3.4e38f;
                #pragma unroll
                for (int i = 0; i < 26; i++) if (i < cnt) mx = fmaxf(mx, q[i]);
                mx = fmaxf(mx, __shfl_xor_sync(0xffffffffu, mx, 1));
                float s = 0.f;
                #pragma unroll
                for (int i = 0; i < 26; i++)
                    if (i < cnt) { q[i] = __expf(q[i] - mx); s += q[i]; }
                s += __shfl_xor_sync(0xffffffffu, s, 1);
                float inv = __fdividef(1.f, s);
                if (act) {
                    const int pb = cbase >> 1;
                    const int np = cnt >> 1;
                    // p[r] -> left-half of row r+1 (pairs pb+pi), right-half of r-1 (+32)
                    #pragma unroll
                    for (int pi = 0; pi < 13; pi++) {
                        if (pi < np) {
                            float pa = q[2 * pi] * inv;
                            float pz = q[2 * pi + 1] * inv;
                            uint32_t ph = bfpack(pa, pz);
                            uint32_t pl = bfpack(pa - bfhi(pa), pz - bfhi(pz));
                            if (r + 1 < RROWS) {
                                AhiU[(r + 1) * AHW + pb + pi] = ph;
                                AloU[(r + 1) * AHW + pb + pi] = pl;
                            }
                            if (r - 1 >= 0) {
                                AhiU[(r - 1) * AHW + 32 + pb + pi] = ph;
                                AloU[(r - 1) * AHW + 32 + pb + pi] = pl;
                            }
                        }
                    }
                }
            }
        }
        __syncthreads();
        if (it == 3) break;

        // ==== MMA: 16 warps = 8 row-blocks x 2 col-halves, bf16 3-split ====
        {
            const int w   = tid >> 5;
            const int l   = tid & 31;
            const int gID = l >> 2;
            const int tID = l & 3;
            const int R0  = 16 * (w >> 1);
            const int nt0 = (w & 1) ? 4 : 0;
            const int ntc = (w & 1) ? 3 : 4;

            float acc[4][4];
            #pragma unroll
            for (int j = 0; j < 4; j++)
                #pragma unroll
                for (int k = 0; k < 4; k++) acc[j][k] = 0.f;

            const uint32_t* Ah = AhiU + (R0 + gID) * AHW + tID;
            const uint32_t* Al = AloU + (R0 + gID) * AHW + tID;
            #pragma unroll
            for (int ks = 0; ks < 8; ks++) {
                const int kb = 8 * ks;
                uint32_t a0h = Ah[kb],           a2h = Ah[kb + 4];
                uint32_t a1h = Ah[8 * AHW + kb], a3h = Ah[8 * AHW + kb + 4];
                uint32_t a0l = Al[kb],           a2l = Al[kb + 4];
                uint32_t a1l = Al[8 * AHW + kb], a3l = Al[8 * AHW + kb + 4];
                const uint4* bp = Bf + (nt0 * 8 + ks) * 32 + l;
                #pragma unroll
                for (int j = 0; j < 4; j++) {
                    if (j < ntc) {                        // warp-uniform guard
                        uint4 b = bp[j * 8 * 32];
                        mma16(acc[j], a0h, a1h, a2h, a3h, b.x, b.y);
                        mma16(acc[j], a0l, a1l, a2l, a3l, b.x, b.y);
                        mma16(acc[j], a0h, a1h, a2h, a3h, b.z, b.w);
                    }
                }
            }
            #pragma unroll
            for (int j = 0; j < 4; j++) {
                if (j < ntc) {
                    int c0 = (nt0 + j) * 8 + 2 * tID;
                    *(float2*)&Dsm[(R0 + gID) * DST + c0] =
                        make_float2(acc[j][0], acc[j][1]);
                    *(float2*)&Dsm[(R0 + gID + 8) * DST + c0] =
                        make_float2(acc[j][2], acc[j][3]);
                }
            }
        }
        __syncthreads();
    }

    // ---- epilogue: coalesced staging -> global ----
    {
        int rows = min(TILE, S_LEN - p0);
        int nvec = rows * L / 4;
        const float4* s4 = (const float4*)(smp + OFF_AHI);
        float4* o4 = (float4*)(out + ((size_t)n * S_LEN + p0) * L);
        for (int i = tid; i < nvec; i += NTHREADS) o4[i] = s4[i];
    }
}

extern "C" void kernel_launch(void* const* d_in, const int* in_sizes, int n_in,
                              void* d_out, int out_size)
{
    const float* unary = (const float*)d_in[0];
    const float* mask  = (const float*)d_in[1];
    const float* T     = (const float*)d_in[2];
    const float* ts    = (const float*)d_in[3];
    const float* te    = (const float*)d_in[4];
    (void)n_in; (void)out_size;

    cudaFuncSetAttribute(mfvi_kernel,
                         cudaFuncAttributeMaxDynamicSharedMemorySize, SMEM_BYTES);

    int NS = in_sizes[1];
    int N  = NS / S_LEN;
    dim3 grid(NTILES, N);
    mfvi_kernel<<<grid, NTHREADS, SMEM_BYTES>>>(unary, mask, T, ts, te, (float*)d_out);
}